// round 12
// baseline (speedup 1.0000x reference)
#include <cuda_runtime.h>
#include <math.h>

#define RCR 5.2f
#define RCA 3.5f
#define NSP 4
#define NATOMS 32
#define NSHFR 16
#define NSHFA 4
#define NSHFZ 8
#define NPAIRBIN 10
#define RAD_FEAT (NSP*NSHFR)            /* 64  */
#define ANG_FEAT (NPAIRBIN*NSHFA*NSHFZ) /* 320 */
#define OUT_FEAT (RAD_FEAT+ANG_FEAT)    /* 384 */
#define MAXATOM 4096
#define PSTRIDE 480                      /* 465 + pads, even */
#define LOG2E 1.4426950408889634f
#define SQRT095 0.97467943448089633f

typedef unsigned long long ull;

// global scratch (static device arrays -- no runtime allocation)
__device__ __align__(16) float g_c[MAXATOM*PSTRIDE];
__device__ __align__(16) float g_s[MAXATOM*PSTRIDE];
__device__ __align__(16) float g_A[MAXATOM*PSTRIDE];
__device__ __align__(16) float g_B[MAXATOM*PSTRIDE];
__device__ int   g_off[MAXATOM*16];

__device__ __forceinline__ float ex2f(float x){ float y; asm("ex2.approx.ftz.f32 %0, %1;":"=f"(y):"f"(x)); return y; }
__device__ __forceinline__ float lg2f(float x){ float y; asm("lg2.approx.ftz.f32 %0, %1;":"=f"(y):"f"(x)); return y; }
__device__ __forceinline__ float sqrt_apx(float x){ float y; asm("sqrt.approx.ftz.f32 %0, %1;":"=f"(y):"f"(x)); return y; }
__device__ __forceinline__ float rsqrt_apx(float x){ float y; asm("rsqrt.approx.ftz.f32 %0, %1;":"=f"(y):"f"(x)); return y; }

__device__ __forceinline__ ull pk2(float lo, float hi){ ull r; asm("mov.b64 %0,{%1,%2};":"=l"(r):"f"(lo),"f"(hi)); return r; }
__device__ __forceinline__ void upk2(ull v, float& lo, float& hi){ asm("mov.b64 {%0,%1},%2;":"=f"(lo),"=f"(hi):"l"(v)); }
__device__ __forceinline__ ull fma2(ull a, ull b, ull c){ ull d; asm("fma.rn.f32x2 %0,%1,%2,%3;":"=l"(d):"l"(a),"l"(b),"l"(c)); return d; }
__device__ __forceinline__ ull mul2(ull a, ull b){ ull d; asm("mul.rn.f32x2 %0,%1,%2;":"=l"(d):"l"(a),"l"(b)); return d; }
__device__ __forceinline__ ull add2(ull a, ull b){ ull d; asm("add.rn.f32x2 %0,%1,%2;":"=l"(d):"l"(a),"l"(b)); return d; }

// ============================================================================
// Kernel R: neighbor build + radial features + pair-record geometry
// ============================================================================
__global__ __launch_bounds__(64) void aev_prep(
    const float* __restrict__ coords,
    const float* __restrict__ etaR_p,
    const float* __restrict__ shfR_p,
    const float* __restrict__ etaA_p,
    const float* __restrict__ zeta_p,
    const int*   __restrict__ species,
    float* __restrict__ out)
{
    __shared__ float s_cx[NATOMS], s_cy[NATOMS], s_cz[NATOMS];
    __shared__ int   s_sp[NATOMS];
    __shared__ float s_shfR[NSHFR];
    __shared__ __align__(16) float4 s_n4[NATOMS];  // ux,uy,uz (x sqrt095), 0.5*d
    __shared__ float  s_nlg[NATOMS];         // lg2(fcA)
    __shared__ int    s_nsp[NATOMS];
    __shared__ int    s_pos[NPAIRBIN];
    __shared__ __align__(16) float s_accR[2][RAD_FEAT];
    __shared__ float  s_etaR, s_etaA, s_zeta;

    const int tid  = threadIdx.x;
    const int w    = tid >> 5;
    const int lane = tid & 31;
    const int atom = blockIdx.x;
    const int mol0 = atom & ~(NATOMS-1);     // first atom of this molecule
    const int i    = atom & (NATOMS-1);

    if (tid < NATOMS) {
        s_cx[tid] = coords[(mol0 + tid)*3 + 0];
        s_cy[tid] = coords[(mol0 + tid)*3 + 1];
        s_cz[tid] = coords[(mol0 + tid)*3 + 2];
        s_sp[tid] = species[mol0 + tid];
        ((float4*)&s_accR[0][0])[tid] = make_float4(0.f,0.f,0.f,0.f); // 32 float4 = 128 f
    } else if (tid < 32 + NSHFR) {
        s_shfR[tid-32] = shfR_p[tid-32];
    } else if (tid == 48) s_etaR = etaR_p[0];
    else if (tid == 49) s_etaA = etaA_p[0];
    else if (tid == 50) s_zeta = zeta_p[0];
    __syncthreads();

    const float zeta  = s_zeta;
    const float nEtaR = -s_etaR * LOG2E;
    const float nEtaA = -s_etaA * LOG2E;
    const bool  z32   = (fabsf(zeta - 32.0f) < 1e-4f);
    const float PI_RCR = 3.14159265358979323846f / RCR;
    const float PI_RCA = 3.14159265358979323846f / RCA;

    // ---- candidate neighbor j = lane (each warp computes; cheap) ----
    const float cix = s_cx[i], ciy = s_cy[i], ciz = s_cz[i];
    const bool  valid_i = (s_sp[i] >= 0);

    float vx = s_cx[lane] - cix;
    float vy = s_cy[lane] - ciy;
    float vz = s_cz[lane] - ciz;
    float d2 = vx*vx + vy*vy + vz*vz;
    float inv = rsqrt_apx(fmaxf(d2, 1e-24f));
    float d   = d2 * inv;
    int   spl = s_sp[lane];
    int   spc = min(max(spl, 0), NSP-1);
    bool  pair_ok = valid_i && (spl >= 0) && (lane != i);

    // ---- radial: 8 shifts per warp, staggered shared atomics ----
    if (pair_ok && d <= RCR) {
        float fcR  = fmaf(0.5f, __cosf(d * PI_RCR), 0.5f);
        float base = 0.25f * fcR;
        float* rad = &s_accR[w][spc * NSHFR];
        int r0 = lane & 15;
        #pragma unroll
        for (int k = w*8; k < w*8 + 8; k++) {
            int r = (r0 + k) & 15;
            float e = d - s_shfR[r];
            atomicAdd(&rad[r], base * ex2f(nEtaR * (e * e)));
        }
    }

    // ---- species-sorted neighbor compaction ----
    bool isnb = pair_ok && (d <= RCA);
    unsigned ms[NSP];
    #pragma unroll
    for (int s = 0; s < NSP; s++)
        ms[s] = __ballot_sync(0xffffffffu, isnb && (spc == s));

    int o1 = __popc(ms[0]);
    int o2 = o1 + __popc(ms[1]);
    int o3 = o2 + __popc(ms[2]);
    int ncA = o3 + __popc(ms[3]);

    if (w == 0 && isnb) {
        unsigned lt = (1u << lane) - 1u;
        int base = (spc == 0) ? 0 : (spc == 1) ? o1 : (spc == 2) ? o2 : o3;
        int pos = base + __popc(ms[spc] & lt);
        float fcA = fmaf(0.5f, __cosf(d * PI_RCA), 0.5f);
        float us  = inv * SQRT095;
        s_n4[pos]  = make_float4(vx*us, vy*us, vz*us, 0.5f*d);
        s_nlg[pos] = lg2f(fcA);
        s_nsp[pos] = spc;
    }

    // ---- closed-form bin counts & even-padded offsets (registers only) ----
    const int n0 = o1, n1 = o2-o1, n2 = o3-o2, n3 = ncA-o3;
    int cnt[NPAIRBIN];
    cnt[0] = (n0*(n0-1))>>1; cnt[1] = n0*n1; cnt[2] = n0*n2; cnt[3] = n0*n3;
    cnt[4] = (n1*(n1-1))>>1; cnt[5] = n1*n2; cnt[6] = n1*n3;
    cnt[7] = (n2*(n2-1))>>1; cnt[8] = n2*n3;
    cnt[9] = (n3*(n3-1))>>1;
    int off[NPAIRBIN+1];
    off[0] = 0;
    #pragma unroll
    for (int bb = 0; bb < NPAIRBIN; bb++) off[bb+1] = off[bb] + ((cnt[bb]+1) & ~1);

    const int rbase = atom * PSTRIDE;
    if (tid <= NPAIRBIN) {
        // constant-indexed select to keep off[]/cnt[] in registers
        int offv = 0, cv = 0;
        #pragma unroll
        for (int bb = 0; bb <= NPAIRBIN; bb++)
            if (tid == bb) { offv = off[bb]; cv = (bb < NPAIRBIN) ? cnt[bb] : 0; }
        g_off[atom*16 + tid] = offv;
        if (tid < NPAIRBIN) {
            s_pos[tid] = offv;
            if (cv & 1) {        // pad record: zero contribution
                int s = rbase + offv + cv;
                g_c[s] = 0.0f; g_s[s] = 0.0f; g_A[s] = -1e30f; g_B[s] = 0.0f;
            }
        }
    }
    __syncthreads();

    // ---- geometry: one lane per pair, bin-sorted records to global ----
    const int P = (ncA * (ncA - 1)) >> 1;
    const float zoff = z32 ? -31.0f : 1.0f;
    const float nEtaA2m = -2.0f * nEtaA;
    {
        const float fn1 = (float)(2*ncA - 1);
        for (int g = tid; g < P; g += 64) {
            float sdisc = sqrtf(fmaf(fn1, fn1, (float)(-8*g)));
            int a = (int)(0.5f * (fn1 - sdisc));
            a = max(a, 0);
            while (a*(ncA-1) - ((a*(a-1))>>1) > g) a--;
            while ((a+1)*(ncA-1) - (((a+1)*a)>>1) <= g) a++;
            int q = g - (a*(ncA-1) - ((a*(a-1))>>1)) + a + 1;

            float4 A4 = s_n4[a];
            float4 B4 = s_n4[q];
            float c  = A4.x*B4.x + A4.y*B4.y + A4.z*B4.z;   // 0.95*cos(theta)
            float st = sqrt_apx(fmaf(-c, c, 1.0f));
            float dm = A4.w + B4.w;
            float lg = s_nlg[a] + s_nlg[q] + zoff;
            int sa = s_nsp[a], sq = s_nsp[q];
            int lo = min(sa, sq), hi = max(sa, sq);
            int pbin = lo*NSP - ((lo*(lo-1))>>1) + (hi - lo);
            int slot = rbase + atomicAdd(&s_pos[pbin], 1);
            g_c[slot] = c;
            g_s[slot] = st;
            g_A[slot] = fmaf(nEtaA * dm, dm, lg);
            g_B[slot] = nEtaA2m * dm;
        }
    }

    // ---- radial write (both banks complete since the pre-geometry barrier) ----
    out[(size_t)atom * OUT_FEAT + tid] = s_accR[0][tid] + s_accR[1][tid];
}

// ============================================================================
// Kernel A: angular consumer (feature-parallel, packed f32x2)
// ============================================================================
__global__ __launch_bounds__(64) void aev_ang(
    const float* __restrict__ etaA_p,
    const float* __restrict__ zeta_p,
    const float* __restrict__ shfA_p,
    const float* __restrict__ shfZ_p,
    float* __restrict__ out)
{
    __shared__ int   s_off[NPAIRBIN+1];
    __shared__ float s_shfA[NSHFA], s_cosZ[NSHFZ], s_sinZ[NSHFZ];
    __shared__ __align__(16) float s_accA[ANG_FEAT];
    __shared__ float s_etaA, s_zeta;

    const int tid  = threadIdx.x;
    const int w    = tid >> 5;
    const int lane = tid & 31;
    const int atom = blockIdx.x;

    if (tid <= NPAIRBIN) {
        s_off[tid] = g_off[atom*16 + tid];
    } else if (tid >= 16 && tid < 16 + NSHFZ) {
        float z = shfZ_p[tid-16];
        s_cosZ[tid-16] = __cosf(z);
        s_sinZ[tid-16] = __sinf(z);
    } else if (tid >= 24 && tid < 24 + NSHFA) {
        s_shfA[tid-24] = shfA_p[tid-24];
    } else if (tid == 28) s_etaA = etaA_p[0];
    else if (tid == 29) s_zeta = zeta_p[0];
    // zero angular bank: 80 float4
    {
        float4* za = (float4*)s_accA;
        za[tid] = make_float4(0.f,0.f,0.f,0.f);
        if (tid < 16) za[tid+64] = make_float4(0.f,0.f,0.f,0.f);
    }
    __syncthreads();

    const float zeta  = s_zeta;
    const float nEtaA = -s_etaA * LOG2E;
    const bool  z32   = (fabsf(zeta - 32.0f) < 1e-4f);

    int off[NPAIRBIN+1];
    #pragma unroll
    for (int bb = 0; bb <= NPAIRBIN; bb++) off[bb] = s_off[bb];
    const int Ptot = off[NPAIRBIN];

    int mid = ((Ptot >> 1) + 1) & ~1;
    if (mid > Ptot) mid = Ptot;
    const int g0 = w ? mid : 0;
    const int g1 = w ? Ptot : mid;

    const float shfA_l = s_shfA[lane >> 3];
    const float cZ = s_cosZ[lane & 7];
    const float sZ = s_sinZ[lane & 7];
    const float Cl = nEtaA * shfA_l * shfA_l;

    const int rbase = atom * PSTRIDE;
    const ull* c2p = (const ull*)(g_c + rbase);
    const ull* s2p = (const ull*)(g_s + rbase);
    const ull* A2p = (const ull*)(g_A + rbase);
    const ull* B2p = (const ull*)(g_B + rbase);

    if (z32) {
        const ull cZ2 = pk2(cZ, cZ), sZ2 = pk2(sZ, sZ);
        const ull shfA2 = pk2(shfA_l, shfA_l), Cl2 = pk2(Cl, Cl);
        const ull one2 = pk2(1.0f, 1.0f);
        #pragma unroll
        for (int bin = 0; bin < NPAIRBIN; bin++) {
            int lo = max(off[bin], g0), hi = min(off[bin+1], g1);
            if (lo >= hi) continue;
            int k0 = lo >> 1, k1 = hi >> 1;
            ull r2 = 0;
            #pragma unroll 2
            for (int k = k0; k < k1; k++) {
                ull c2 = __ldg(c2p + k);           // LDG.64 broadcast
                ull s2 = __ldg(s2p + k);
                ull A2 = __ldg(A2p + k);
                ull B2 = __ldg(B2p + k);
                ull t2 = fma2(s2, sZ2, one2);
                ull y  = fma2(c2, cZ2, t2);        // 1 + cos(theta - ShfZ)
                ull yy2 = mul2(y, y);
                ull y4 = mul2(yy2, yy2);
                ull y8 = mul2(y4, y4);
                ull y16 = mul2(y8, y8);
                ull y32 = mul2(y16, y16);
                ull arg = add2(fma2(B2, shfA2, A2), Cl2);
                float alo, ahi; upk2(arg, alo, ahi);
                ull e2 = pk2(ex2f(alo), ex2f(ahi));
                r2 = fma2(y32, e2, r2);
            }
            float rlo, rhi; upk2(r2, rlo, rhi);
            atomicAdd(&s_accA[bin*32 + lane], rlo + rhi);
        }
    } else {
        #pragma unroll
        for (int bin = 0; bin < NPAIRBIN; bin++) {
            int lo = max(off[bin], g0), hi = min(off[bin+1], g1);
            if (lo >= hi) continue;
            float r = 0.0f;
            for (int g = lo; g < hi; g++) {
                float t = fmaf(g_s[rbase+g], sZ, 1.0f);
                float y = fmaf(g_c[rbase+g], cZ, t);
                float f1 = __powf(0.5f * y, zeta);
                float arg = fmaf(g_B[rbase+g], shfA_l, g_A[rbase+g]) + Cl;
                r = fmaf(f1, ex2f(arg), r);
            }
            atomicAdd(&s_accA[bin*32 + lane], r);
        }
    }
    __syncthreads();

    float* op = out + (size_t)atom * OUT_FEAT + RAD_FEAT;
    #pragma unroll
    for (int f = tid; f < ANG_FEAT; f += 64)
        op[f] = s_accA[f];
}

extern "C" void kernel_launch(void* const* d_in, const int* in_sizes, int n_in,
                              void* d_out, int out_size)
{
    const float* coords = (const float*)d_in[0];
    const float* etaR   = (const float*)d_in[1];
    const float* shfR   = (const float*)d_in[2];
    const float* etaA   = (const float*)d_in[3];
    const float* zeta   = (const float*)d_in[4];
    const float* shfA   = (const float*)d_in[5];
    const float* shfZ   = (const float*)d_in[6];
    const int*   spec   = (const int*)d_in[7];
    float* out = (float*)d_out;

    int B = in_sizes[0] / (NATOMS*3);
    int natoms = B * NATOMS;
    aev_prep<<<natoms, 64>>>(coords, etaR, shfR, etaA, zeta, spec, out);
    aev_ang <<<natoms, 64>>>(etaA, zeta, shfA, shfZ, out);
}

// round 13
// speedup vs baseline: 1.0168x; 1.0168x over previous
#include <cuda_runtime.h>
#include <math.h>

#define RCR 5.2f
#define RCA 3.5f
#define NSP 4
#define NATOMS 32
#define NSHFR 16
#define NSHFA 4
#define NSHFZ 8
#define NPAIRBIN 10
#define RAD_FEAT (NSP*NSHFR)            /* 64  */
#define ANG_FEAT (NPAIRBIN*NSHFA*NSHFZ) /* 320 */
#define OUT_FEAT (RAD_FEAT+ANG_FEAT)    /* 384 */
#define MAXATOM 4096
#define PSTRIDE 480                      /* 465 + pads, even */
#define LOG2E 1.4426950408889634f
#define SQRT095 0.97467943448089633f

typedef unsigned long long ull;

// global scratch (static device arrays -- no runtime allocation)
__device__ __align__(16) float g_c[MAXATOM*PSTRIDE];
__device__ __align__(16) float g_s[MAXATOM*PSTRIDE];
__device__ __align__(16) float g_A[MAXATOM*PSTRIDE];
__device__ __align__(16) float g_B[MAXATOM*PSTRIDE];
__device__ int   g_off[MAXATOM*16];

__device__ __forceinline__ float ex2f(float x){ float y; asm("ex2.approx.ftz.f32 %0, %1;":"=f"(y):"f"(x)); return y; }
__device__ __forceinline__ float lg2f(float x){ float y; asm("lg2.approx.ftz.f32 %0, %1;":"=f"(y):"f"(x)); return y; }
__device__ __forceinline__ float sqrt_apx(float x){ float y; asm("sqrt.approx.ftz.f32 %0, %1;":"=f"(y):"f"(x)); return y; }
__device__ __forceinline__ float rsqrt_apx(float x){ float y; asm("rsqrt.approx.ftz.f32 %0, %1;":"=f"(y):"f"(x)); return y; }

__device__ __forceinline__ ull pk2(float lo, float hi){ ull r; asm("mov.b64 %0,{%1,%2};":"=l"(r):"f"(lo),"f"(hi)); return r; }
__device__ __forceinline__ void upk2(ull v, float& lo, float& hi){ asm("mov.b64 {%0,%1},%2;":"=f"(lo),"=f"(hi):"l"(v)); }
__device__ __forceinline__ ull fma2(ull a, ull b, ull c){ ull d; asm("fma.rn.f32x2 %0,%1,%2,%3;":"=l"(d):"l"(a),"l"(b),"l"(c)); return d; }
__device__ __forceinline__ ull mul2(ull a, ull b){ ull d; asm("mul.rn.f32x2 %0,%1,%2;":"=l"(d):"l"(a),"l"(b)); return d; }
__device__ __forceinline__ ull add2(ull a, ull b){ ull d; asm("add.rn.f32x2 %0,%1,%2;":"=l"(d):"l"(a),"l"(b)); return d; }

// ============================================================================
// Kernel R: neighbor build + radial features + pair-record geometry
// ============================================================================
__global__ __launch_bounds__(64) void aev_prep(
    const float* __restrict__ coords,
    const float* __restrict__ etaR_p,
    const float* __restrict__ shfR_p,
    const float* __restrict__ etaA_p,
    const float* __restrict__ zeta_p,
    const int*   __restrict__ species,
    float* __restrict__ out)
{
    __shared__ float s_cx[NATOMS], s_cy[NATOMS], s_cz[NATOMS];
    __shared__ int   s_sp[NATOMS];
    __shared__ float s_shfR[NSHFR];
    __shared__ __align__(16) float4 s_n4[NATOMS];  // ux,uy,uz (x sqrt095), 0.5*d
    __shared__ float  s_nlg[NATOMS];         // lg2(fcA)
    __shared__ int    s_nsp[NATOMS];
    __shared__ int    s_pos[NPAIRBIN];
    __shared__ __align__(16) float s_accR[2][RAD_FEAT];
    __shared__ float  s_etaR, s_etaA, s_zeta;

    const int tid  = threadIdx.x;
    const int w    = tid >> 5;
    const int lane = tid & 31;
    const int atom = blockIdx.x;
    const int mol0 = atom & ~(NATOMS-1);     // first atom of this molecule
    const int i    = atom & (NATOMS-1);

    if (tid < NATOMS) {
        s_cx[tid] = coords[(mol0 + tid)*3 + 0];
        s_cy[tid] = coords[(mol0 + tid)*3 + 1];
        s_cz[tid] = coords[(mol0 + tid)*3 + 2];
        s_sp[tid] = species[mol0 + tid];
        ((float4*)&s_accR[0][0])[tid] = make_float4(0.f,0.f,0.f,0.f); // 32 float4 = 128 f
    } else if (tid < 32 + NSHFR) {
        s_shfR[tid-32] = shfR_p[tid-32];
    } else if (tid == 48) s_etaR = etaR_p[0];
    else if (tid == 49) s_etaA = etaA_p[0];
    else if (tid == 50) s_zeta = zeta_p[0];
    __syncthreads();

    const float zeta  = s_zeta;
    const float nEtaR = -s_etaR * LOG2E;
    const float nEtaA = -s_etaA * LOG2E;
    const bool  z32   = (fabsf(zeta - 32.0f) < 1e-4f);
    const float PI_RCR = 3.14159265358979323846f / RCR;
    const float PI_RCA = 3.14159265358979323846f / RCA;

    // ---- candidate neighbor j = lane (each warp computes; cheap) ----
    const float cix = s_cx[i], ciy = s_cy[i], ciz = s_cz[i];
    const bool  valid_i = (s_sp[i] >= 0);

    float vx = s_cx[lane] - cix;
    float vy = s_cy[lane] - ciy;
    float vz = s_cz[lane] - ciz;
    float d2 = vx*vx + vy*vy + vz*vz;
    float inv = rsqrt_apx(fmaxf(d2, 1e-24f));
    float d   = d2 * inv;
    int   spl = s_sp[lane];
    int   spc = min(max(spl, 0), NSP-1);
    bool  pair_ok = valid_i && (spl >= 0) && (lane != i);

    // ---- radial: 8 shifts per warp, staggered shared atomics ----
    if (pair_ok && d <= RCR) {
        float fcR  = fmaf(0.5f, __cosf(d * PI_RCR), 0.5f);
        float base = 0.25f * fcR;
        float* rad = &s_accR[w][spc * NSHFR];
        int r0 = lane & 15;
        #pragma unroll
        for (int k = w*8; k < w*8 + 8; k++) {
            int r = (r0 + k) & 15;
            float e = d - s_shfR[r];
            atomicAdd(&rad[r], base * ex2f(nEtaR * (e * e)));
        }
    }

    // ---- species-sorted neighbor compaction ----
    bool isnb = pair_ok && (d <= RCA);
    unsigned ms[NSP];
    #pragma unroll
    for (int s = 0; s < NSP; s++)
        ms[s] = __ballot_sync(0xffffffffu, isnb && (spc == s));

    int o1 = __popc(ms[0]);
    int o2 = o1 + __popc(ms[1]);
    int o3 = o2 + __popc(ms[2]);
    int ncA = o3 + __popc(ms[3]);

    if (w == 0 && isnb) {
        unsigned lt = (1u << lane) - 1u;
        int base = (spc == 0) ? 0 : (spc == 1) ? o1 : (spc == 2) ? o2 : o3;
        int pos = base + __popc(ms[spc] & lt);
        float fcA = fmaf(0.5f, __cosf(d * PI_RCA), 0.5f);
        float us  = inv * SQRT095;
        s_n4[pos]  = make_float4(vx*us, vy*us, vz*us, 0.5f*d);
        s_nlg[pos] = lg2f(fcA);
        s_nsp[pos] = spc;
    }

    // ---- closed-form bin counts & even-padded offsets (registers only) ----
    const int n0 = o1, n1 = o2-o1, n2 = o3-o2, n3 = ncA-o3;
    int cnt[NPAIRBIN];
    cnt[0] = (n0*(n0-1))>>1; cnt[1] = n0*n1; cnt[2] = n0*n2; cnt[3] = n0*n3;
    cnt[4] = (n1*(n1-1))>>1; cnt[5] = n1*n2; cnt[6] = n1*n3;
    cnt[7] = (n2*(n2-1))>>1; cnt[8] = n2*n3;
    cnt[9] = (n3*(n3-1))>>1;
    int off[NPAIRBIN+1];
    off[0] = 0;
    #pragma unroll
    for (int bb = 0; bb < NPAIRBIN; bb++) off[bb+1] = off[bb] + ((cnt[bb]+1) & ~1);

    const int rbase = atom * PSTRIDE;
    if (tid <= NPAIRBIN) {
        // constant-indexed select to keep off[]/cnt[] in registers
        int offv = 0, cv = 0;
        #pragma unroll
        for (int bb = 0; bb <= NPAIRBIN; bb++)
            if (tid == bb) { offv = off[bb]; cv = (bb < NPAIRBIN) ? cnt[bb] : 0; }
        g_off[atom*16 + tid] = offv;
        if (tid < NPAIRBIN) {
            s_pos[tid] = offv;
            if (cv & 1) {        // pad record: zero contribution
                int s = rbase + offv + cv;
                g_c[s] = 0.0f; g_s[s] = 0.0f; g_A[s] = -1e30f; g_B[s] = 0.0f;
            }
        }
    }
    __syncthreads();

    // ---- geometry: one lane per pair, bin-sorted records to global ----
    const int P = (ncA * (ncA - 1)) >> 1;
    const float zoff = z32 ? -31.0f : 1.0f;
    const float nEtaA2m = -2.0f * nEtaA;
    {
        const float fn1 = (float)(2*ncA - 1);
        for (int g = tid; g < P; g += 64) {
            float sdisc = sqrtf(fmaf(fn1, fn1, (float)(-8*g)));
            int a = (int)(0.5f * (fn1 - sdisc));
            a = max(a, 0);
            while (a*(ncA-1) - ((a*(a-1))>>1) > g) a--;
            while ((a+1)*(ncA-1) - (((a+1)*a)>>1) <= g) a++;
            int q = g - (a*(ncA-1) - ((a*(a-1))>>1)) + a + 1;

            float4 A4 = s_n4[a];
            float4 B4 = s_n4[q];
            float c  = A4.x*B4.x + A4.y*B4.y + A4.z*B4.z;   // 0.95*cos(theta)
            float st = sqrt_apx(fmaf(-c, c, 1.0f));
            float dm = A4.w + B4.w;
            float lg = s_nlg[a] + s_nlg[q] + zoff;
            int sa = s_nsp[a], sq = s_nsp[q];
            int lo = min(sa, sq), hi = max(sa, sq);
            int pbin = lo*NSP - ((lo*(lo-1))>>1) + (hi - lo);
            int slot = rbase + atomicAdd(&s_pos[pbin], 1);
            g_c[slot] = c;
            g_s[slot] = st;
            g_A[slot] = fmaf(nEtaA * dm, dm, lg);
            g_B[slot] = nEtaA2m * dm;
        }
    }

    // ---- radial write (both banks complete since the pre-geometry barrier) ----
    out[(size_t)atom * OUT_FEAT + tid] = s_accR[0][tid] + s_accR[1][tid];
}

// ============================================================================
// Kernel A: angular consumer — SMEM-staged records, packed f32x2, 4 warps
// ============================================================================
__global__ __launch_bounds__(128) void aev_ang(
    const float* __restrict__ etaA_p,
    const float* __restrict__ zeta_p,
    const float* __restrict__ shfA_p,
    const float* __restrict__ shfZ_p,
    float* __restrict__ out)
{
    __shared__ int   s_off[NPAIRBIN+1];
    __shared__ float s_shfA[NSHFA], s_cosZ[NSHFZ], s_sinZ[NSHFZ];
    __shared__ __align__(16) ull s_c2[PSTRIDE/2];
    __shared__ __align__(16) ull s_s2[PSTRIDE/2];
    __shared__ __align__(16) ull s_A2[PSTRIDE/2];
    __shared__ __align__(16) ull s_B2[PSTRIDE/2];
    __shared__ __align__(16) float s_accA[ANG_FEAT];
    __shared__ float s_etaA, s_zeta;

    const int tid  = threadIdx.x;
    const int w    = tid >> 5;
    const int lane = tid & 31;
    const int atom = blockIdx.x;

    if (tid <= NPAIRBIN) {
        s_off[tid] = g_off[atom*16 + tid];
    } else if (tid >= 16 && tid < 16 + NSHFZ) {
        float z = shfZ_p[tid-16];
        s_cosZ[tid-16] = __cosf(z);
        s_sinZ[tid-16] = __sinf(z);
    } else if (tid >= 24 && tid < 24 + NSHFA) {
        s_shfA[tid-24] = shfA_p[tid-24];
    } else if (tid == 28) s_etaA = etaA_p[0];
    else if (tid == 29) s_zeta = zeta_p[0];
    // zero angular bank: 80 float4 over 128 threads
    if (tid < 80) ((float4*)s_accA)[tid] = make_float4(0.f,0.f,0.f,0.f);
    __syncthreads();

    int off[NPAIRBIN+1];
    #pragma unroll
    for (int bb = 0; bb <= NPAIRBIN; bb++) off[bb] = s_off[bb];
    const int Ptot = off[NPAIRBIN];
    const int K = Ptot >> 1;                 // packed record count (Ptot even)

    // ---- bulk stage: coalesced global -> shared (high MLP) ----
    {
        const int rb2 = (atom * PSTRIDE) >> 1;
        const ull* c2p = (const ull*)g_c + rb2;
        const ull* s2p = (const ull*)g_s + rb2;
        const ull* A2p = (const ull*)g_A + rb2;
        const ull* B2p = (const ull*)g_B + rb2;
        for (int k = tid; k < K; k += 128) {
            s_c2[k] = __ldg(c2p + k);
            s_s2[k] = __ldg(s2p + k);
            s_A2[k] = __ldg(A2p + k);
            s_B2[k] = __ldg(B2p + k);
        }
    }
    __syncthreads();

    const float zeta  = s_zeta;
    const float nEtaA = -s_etaA * LOG2E;
    const bool  z32   = (fabsf(zeta - 32.0f) < 1e-4f);

    const int g0 = ((Ptot * w) >> 2) & ~1;
    const int g1 = (w == 3) ? Ptot : (((Ptot * (w+1)) >> 2) & ~1);

    const float shfA_l = s_shfA[lane >> 3];
    const float cZ = s_cosZ[lane & 7];
    const float sZ = s_sinZ[lane & 7];
    const float Cl = nEtaA * shfA_l * shfA_l;

    if (z32) {
        const ull cZ2 = pk2(cZ, cZ), sZ2 = pk2(sZ, sZ);
        const ull shfA2 = pk2(shfA_l, shfA_l), Cl2 = pk2(Cl, Cl);
        const ull one2 = pk2(1.0f, 1.0f);
        #pragma unroll
        for (int bin = 0; bin < NPAIRBIN; bin++) {
            int lo = max(off[bin], g0), hi = min(off[bin+1], g1);
            if (lo >= hi) continue;
            int k0 = lo >> 1, k1 = hi >> 1;
            ull r2 = 0;
            #pragma unroll 2
            for (int k = k0; k < k1; k++) {
                ull c2 = s_c2[k];                  // LDS.64 broadcast
                ull s2 = s_s2[k];
                ull A2 = s_A2[k];
                ull B2 = s_B2[k];
                ull t2 = fma2(s2, sZ2, one2);
                ull y  = fma2(c2, cZ2, t2);        // 1 + cos(theta - ShfZ)
                ull yy2 = mul2(y, y);
                ull y4 = mul2(yy2, yy2);
                ull y8 = mul2(y4, y4);
                ull y16 = mul2(y8, y8);
                ull y32 = mul2(y16, y16);
                ull arg = add2(fma2(B2, shfA2, A2), Cl2);
                float alo, ahi; upk2(arg, alo, ahi);
                ull e2 = pk2(ex2f(alo), ex2f(ahi));
                r2 = fma2(y32, e2, r2);
            }
            float rlo, rhi; upk2(r2, rlo, rhi);
            atomicAdd(&s_accA[bin*32 + lane], rlo + rhi);
        }
    } else {
        const float* cf = (const float*)s_c2;
        const float* sf = (const float*)s_s2;
        const float* Af = (const float*)s_A2;
        const float* Bf = (const float*)s_B2;
        #pragma unroll
        for (int bin = 0; bin < NPAIRBIN; bin++) {
            int lo = max(off[bin], g0), hi = min(off[bin+1], g1);
            if (lo >= hi) continue;
            float r = 0.0f;
            for (int g = lo; g < hi; g++) {
                float t = fmaf(sf[g], sZ, 1.0f);
                float y = fmaf(cf[g], cZ, t);
                float f1 = __powf(0.5f * y, zeta);
                float arg = fmaf(Bf[g], shfA_l, Af[g]) + Cl;
                r = fmaf(f1, ex2f(arg), r);
            }
            atomicAdd(&s_accA[bin*32 + lane], r);
        }
    }
    __syncthreads();

    float* op = out + (size_t)atom * OUT_FEAT + RAD_FEAT;
    #pragma unroll
    for (int f = tid; f < ANG_FEAT; f += 128)
        op[f] = s_accA[f];
}

extern "C" void kernel_launch(void* const* d_in, const int* in_sizes, int n_in,
                              void* d_out, int out_size)
{
    const float* coords = (const float*)d_in[0];
    const float* etaR   = (const float*)d_in[1];
    const float* shfR   = (const float*)d_in[2];
    const float* etaA   = (const float*)d_in[3];
    const float* zeta   = (const float*)d_in[4];
    const float* shfA   = (const float*)d_in[5];
    const float* shfZ   = (const float*)d_in[6];
    const int*   spec   = (const int*)d_in[7];
    float* out = (float*)d_out;

    int B = in_sizes[0] / (NATOMS*3);
    int natoms = B * NATOMS;
    aev_prep<<<natoms, 64>>>(coords, etaR, shfR, etaA, zeta, spec, out);
    aev_ang <<<natoms, 128>>>(etaA, zeta, shfA, shfZ, out);
}

// round 14
// speedup vs baseline: 1.0886x; 1.0706x over previous
#include <cuda_runtime.h>
#include <math.h>

#define RCR 5.2f
#define RCA 3.5f
#define NSP 4
#define NATOMS 32
#define NSHFR 16
#define NSHFA 4
#define NSHFZ 8
#define NPAIRBIN 10
#define RAD_FEAT (NSP*NSHFR)            /* 64  */
#define ANG_FEAT (NPAIRBIN*NSHFA*NSHFZ) /* 320 */
#define OUT_FEAT (RAD_FEAT+ANG_FEAT)    /* 384 */
#define NW 4                             /* warps (= atoms) per block */
#define ARENA 240                        /* ull per array per warp: 480 floats >= 465+10 pads */
#define LOG2E 1.4426950408889634f
#define SQRT095 0.97467943448089633f

typedef unsigned long long ull;

__device__ __forceinline__ float ex2f(float x){ float y; asm("ex2.approx.ftz.f32 %0, %1;":"=f"(y):"f"(x)); return y; }
__device__ __forceinline__ float lg2f(float x){ float y; asm("lg2.approx.ftz.f32 %0, %1;":"=f"(y):"f"(x)); return y; }
__device__ __forceinline__ float sqrt_apx(float x){ float y; asm("sqrt.approx.ftz.f32 %0, %1;":"=f"(y):"f"(x)); return y; }
__device__ __forceinline__ float rsqrt_apx(float x){ float y; asm("rsqrt.approx.ftz.f32 %0, %1;":"=f"(y):"f"(x)); return y; }

__device__ __forceinline__ ull pk2(float lo, float hi){ ull r; asm("mov.b64 %0,{%1,%2};":"=l"(r):"f"(lo),"f"(hi)); return r; }
__device__ __forceinline__ void upk2(ull v, float& lo, float& hi){ asm("mov.b64 {%0,%1},%2;":"=f"(lo),"=f"(hi):"l"(v)); }
__device__ __forceinline__ ull fma2(ull a, ull b, ull c){ ull d; asm("fma.rn.f32x2 %0,%1,%2,%3;":"=l"(d):"l"(a),"l"(b),"l"(c)); return d; }
__device__ __forceinline__ ull mul2(ull a, ull b){ ull d; asm("mul.rn.f32x2 %0,%1,%2;":"=l"(d):"l"(a),"l"(b)); return d; }
__device__ __forceinline__ ull add2(ull a, ull b){ ull d; asm("add.rn.f32x2 %0,%1,%2;":"=l"(d):"l"(a),"l"(b)); return d; }

__global__ __launch_bounds__(NW*32) void aev_kernel(
    const float* __restrict__ coords,
    const float* __restrict__ etaR_p,
    const float* __restrict__ shfR_p,
    const float* __restrict__ etaA_p,
    const float* __restrict__ zeta_p,
    const float* __restrict__ shfA_p,
    const float* __restrict__ shfZ_p,
    const int*   __restrict__ species,
    float* __restrict__ out)
{
    __shared__ float s_cx[NATOMS], s_cy[NATOMS], s_cz[NATOMS];
    __shared__ int   s_sp[NATOMS];
    __shared__ float s_shfR[NSHFR], s_shfA[NSHFA];
    __shared__ float s_cosZ[NSHFZ], s_sinZ[NSHFZ];
    __shared__ float s_etaR, s_etaA, s_zeta;
    // per-warp private state
    __shared__ __align__(16) float4 s_n4[NW][NATOMS];   // ux,uy,uz (x sqrt095), 0.5*d
    __shared__ float s_nlg[NW][NATOMS];
    __shared__ int   s_nsp[NW][NATOMS];
    __shared__ int   s_pos[NW][NPAIRBIN];
    __shared__ __align__(16) ull s_c2[NW][ARENA];
    __shared__ __align__(16) ull s_s2[NW][ARENA];
    __shared__ __align__(16) ull s_A2[NW][ARENA];
    __shared__ __align__(16) ull s_B2[NW][ARENA];
    __shared__ __align__(16) float s_accR[NW][RAD_FEAT];

    const int tid  = threadIdx.x;
    const int w    = tid >> 5;
    const int lane = tid & 31;
    const int mol0 = (blockIdx.x >> 3) << 5;       // first atom of molecule
    const int i    = ((blockIdx.x & 7) << 2) + w;  // local atom index for this warp
    const int atom = mol0 + i;

    // ---- block-wide loads (one sync; warps independent afterwards) ----
    if (tid < NATOMS) {
        s_cx[tid] = coords[(mol0 + tid)*3 + 0];
        s_cy[tid] = coords[(mol0 + tid)*3 + 1];
        s_cz[tid] = coords[(mol0 + tid)*3 + 2];
        s_sp[tid] = species[mol0 + tid];
    } else if (tid < 32 + NSHFR) {
        s_shfR[tid-32] = shfR_p[tid-32];
    } else if (tid < 48 + NSHFA) {
        s_shfA[tid-48] = shfA_p[tid-48];
    } else if (tid < 55) {
        if (tid == 52) s_etaR = etaR_p[0];
        if (tid == 53) s_etaA = etaA_p[0];
        if (tid == 54) s_zeta = zeta_p[0];
    } else if (tid >= 56 && tid < 64) {
        float z = shfZ_p[tid-56];
        s_cosZ[tid-56] = __cosf(z);
        s_sinZ[tid-56] = __sinf(z);
    }
    __syncthreads();

    const float zeta  = s_zeta;
    const float nEtaR = -s_etaR * LOG2E;
    const float nEtaA = -s_etaA * LOG2E;
    const bool  z32   = (fabsf(zeta - 32.0f) < 1e-4f);
    const float PI_RCR = 3.14159265358979323846f / RCR;
    const float PI_RCA = 3.14159265358979323846f / RCA;

    // ---- per-warp: candidate neighbor j = lane ----
    const float cix = s_cx[i], ciy = s_cy[i], ciz = s_cz[i];
    const bool  valid_i = (s_sp[i] >= 0);

    float vx = s_cx[lane] - cix;
    float vy = s_cy[lane] - ciy;
    float vz = s_cz[lane] - ciz;
    float d2 = vx*vx + vy*vy + vz*vz;
    float inv = rsqrt_apx(fmaxf(d2, 1e-24f));
    float d   = d2 * inv;
    int   spl = s_sp[lane];
    int   spc = min(max(spl, 0), NSP-1);
    bool  pair_ok = valid_i && (spl >= 0) && (lane != i);

    // ---- radial: private bank, staggered atomics, direct store ----
    s_accR[w][lane] = 0.0f;
    s_accR[w][lane + 32] = 0.0f;
    __syncwarp();
    if (pair_ok && d <= RCR) {
        float fcR  = fmaf(0.5f, __cosf(d * PI_RCR), 0.5f);
        float base = 0.25f * fcR;
        float* rad = &s_accR[w][spc * NSHFR];
        int r0 = lane & 15;
        #pragma unroll
        for (int k = 0; k < NSHFR; k++) {
            int r = (r0 + k) & 15;
            float e = d - s_shfR[r];
            atomicAdd(&rad[r], base * ex2f(nEtaR * (e * e)));
        }
    }

    // ---- species-sorted neighbor compaction (per warp) ----
    bool isnb = pair_ok && (d <= RCA);
    unsigned ms[NSP];
    #pragma unroll
    for (int s = 0; s < NSP; s++)
        ms[s] = __ballot_sync(0xffffffffu, isnb && (spc == s));

    int o1 = __popc(ms[0]);
    int o2 = o1 + __popc(ms[1]);
    int o3 = o2 + __popc(ms[2]);
    int ncA = o3 + __popc(ms[3]);

    if (isnb) {
        unsigned lt = (1u << lane) - 1u;
        int base = (spc == 0) ? 0 : (spc == 1) ? o1 : (spc == 2) ? o2 : o3;
        int pos = base + __popc(ms[spc] & lt);
        float fcA = fmaf(0.5f, __cosf(d * PI_RCA), 0.5f);
        float us  = inv * SQRT095;
        s_n4[w][pos]  = make_float4(vx*us, vy*us, vz*us, 0.5f*d);
        s_nlg[w][pos] = lg2f(fcA);
        s_nsp[w][pos] = spc;
    }

    // ---- closed-form bin counts & even-padded offsets (registers) ----
    const int n0 = o1, n1 = o2-o1, n2 = o3-o2, n3 = ncA-o3;
    int cnt[NPAIRBIN];
    cnt[0] = (n0*(n0-1))>>1; cnt[1] = n0*n1; cnt[2] = n0*n2; cnt[3] = n0*n3;
    cnt[4] = (n1*(n1-1))>>1; cnt[5] = n1*n2; cnt[6] = n1*n3;
    cnt[7] = (n2*(n2-1))>>1; cnt[8] = n2*n3;
    cnt[9] = (n3*(n3-1))>>1;
    int off[NPAIRBIN+1];
    off[0] = 0;
    #pragma unroll
    for (int bb = 0; bb < NPAIRBIN; bb++) off[bb+1] = off[bb] + ((cnt[bb]+1) & ~1);

    if (lane < NPAIRBIN) {
        int offv = 0, cv = 0;
        #pragma unroll
        for (int bb = 0; bb < NPAIRBIN; bb++)
            if (lane == bb) { offv = off[bb]; cv = cnt[bb]; }
        s_pos[w][lane] = offv;
        if (cv & 1) {        // pad record: ex2(-1e30) -> 0 contribution
            int s = offv + cv;
            ((float*)s_c2[w])[s] = 0.0f;
            ((float*)s_s2[w])[s] = 0.0f;
            ((float*)s_A2[w])[s] = -1e30f;
            ((float*)s_B2[w])[s] = 0.0f;
        }
    }
    __syncwarp();

    // ---- geometry: lanes stride over flat pairs, bin-sorted into arena ----
    const int P = (ncA * (ncA - 1)) >> 1;
    const float zoff = z32 ? -31.0f : 1.0f;
    const float nEtaA2m = -2.0f * nEtaA;
    {
        const float fn1 = (float)(2*ncA - 1);
        for (int g = lane; g < P; g += 32) {
            float sdisc = sqrtf(fmaf(fn1, fn1, (float)(-8*g)));
            int a = (int)(0.5f * (fn1 - sdisc));
            a = max(a, 0);
            while (a*(ncA-1) - ((a*(a-1))>>1) > g) a--;
            while ((a+1)*(ncA-1) - (((a+1)*a)>>1) <= g) a++;
            int q = g - (a*(ncA-1) - ((a*(a-1))>>1)) + a + 1;

            float4 A4 = s_n4[w][a];
            float4 B4 = s_n4[w][q];
            float c  = A4.x*B4.x + A4.y*B4.y + A4.z*B4.z;   // 0.95*cos(theta)
            float st = sqrt_apx(fmaf(-c, c, 1.0f));
            float dm = A4.w + B4.w;
            float lg = s_nlg[w][a] + s_nlg[w][q] + zoff;
            int sa = s_nsp[w][a], sq = s_nsp[w][q];
            int lo = min(sa, sq), hi = max(sa, sq);
            int pbin = lo*NSP - ((lo*(lo-1))>>1) + (hi - lo);
            int slot = atomicAdd(&s_pos[w][pbin], 1);
            ((float*)s_c2[w])[slot] = c;
            ((float*)s_s2[w])[slot] = st;
            ((float*)s_A2[w])[slot] = fmaf(nEtaA * dm, dm, lg);
            ((float*)s_B2[w])[slot] = nEtaA2m * dm;
        }
    }
    __syncwarp();

    // ---- radial write (atomics complete for this warp) ----
    float* op = out + (size_t)atom * OUT_FEAT;
    op[lane]      = s_accR[w][lane];
    op[lane + 32] = s_accR[w][lane + 32];

    // ---- consume: bin-sequential, register accumulator, direct STG ----
    const float shfA_l = s_shfA[lane >> 3];
    const float cZ = s_cosZ[lane & 7];
    const float sZ = s_sinZ[lane & 7];
    const float Cl = nEtaA * shfA_l * shfA_l;
    float* oa = op + RAD_FEAT;

    if (z32) {
        const ull cZ2 = pk2(cZ, cZ), sZ2 = pk2(sZ, sZ);
        const ull shfA2 = pk2(shfA_l, shfA_l), Cl2 = pk2(Cl, Cl);
        const ull one2 = pk2(1.0f, 1.0f);
        #pragma unroll
        for (int bin = 0; bin < NPAIRBIN; bin++) {
            int k0 = off[bin] >> 1, k1 = off[bin+1] >> 1;
            ull r2 = 0;
            #pragma unroll 2
            for (int k = k0; k < k1; k++) {
                ull c2 = s_c2[w][k];               // LDS.64 broadcast
                ull s2 = s_s2[w][k];
                ull A2 = s_A2[w][k];
                ull B2 = s_B2[w][k];
                ull t2 = fma2(s2, sZ2, one2);
                ull y  = fma2(c2, cZ2, t2);        // 1 + cos(theta - ShfZ)
                ull yy2 = mul2(y, y);
                ull y4 = mul2(yy2, yy2);
                ull y8 = mul2(y4, y4);
                ull y16 = mul2(y8, y8);
                ull y32 = mul2(y16, y16);
                ull arg = add2(fma2(B2, shfA2, A2), Cl2);
                float alo, ahi; upk2(arg, alo, ahi);
                ull e2 = pk2(ex2f(alo), ex2f(ahi));
                r2 = fma2(y32, e2, r2);
            }
            float rlo, rhi; upk2(r2, rlo, rhi);
            oa[bin*32 + lane] = rlo + rhi;
        }
    } else {
        const float* cf = (const float*)s_c2[w];
        const float* sf = (const float*)s_s2[w];
        const float* Af = (const float*)s_A2[w];
        const float* Bf = (const float*)s_B2[w];
        #pragma unroll
        for (int bin = 0; bin < NPAIRBIN; bin++) {
            int lo = off[bin], hi = off[bin+1];
            float r = 0.0f;
            for (int g = lo; g < hi; g++) {
                float t = fmaf(sf[g], sZ, 1.0f);
                float y = fmaf(cf[g], cZ, t);
                float f1 = __powf(0.5f * y, zeta);
                float arg = fmaf(Bf[g], shfA_l, Af[g]) + Cl;
                r = fmaf(f1, ex2f(arg), r);
            }
            oa[bin*32 + lane] = r;
        }
    }
}

extern "C" void kernel_launch(void* const* d_in, const int* in_sizes, int n_in,
                              void* d_out, int out_size)
{
    const float* coords = (const float*)d_in[0];
    const float* etaR   = (const float*)d_in[1];
    const float* shfR   = (const float*)d_in[2];
    const float* etaA   = (const float*)d_in[3];
    const float* zeta   = (const float*)d_in[4];
    const float* shfA   = (const float*)d_in[5];
    const float* shfZ   = (const float*)d_in[6];
    const int*   spec   = (const int*)d_in[7];
    float* out = (float*)d_out;

    int B = in_sizes[0] / (NATOMS*3);
    dim3 grid(B * 8);   // 4 atoms per block (one per warp)
    aev_kernel<<<grid, NW*32>>>(coords, etaR, shfR, etaA, zeta, shfA, shfZ, spec, out);
}

// round 16
// speedup vs baseline: 1.2790x; 1.1750x over previous
#include <cuda_runtime.h>
#include <math.h>

#define RCR 5.2f
#define RCA 3.5f
#define NSP 4
#define NATOMS 32
#define NSHFR 16
#define NSHFA 4
#define NSHFZ 8
#define NPAIRBIN 10
#define RAD_FEAT (NSP*NSHFR)            /* 64  */
#define ANG_FEAT (NPAIRBIN*NSHFA*NSHFZ) /* 320 */
#define OUT_FEAT (RAD_FEAT+ANG_FEAT)    /* 384 */
#define AWARPS 4
#define KMAX 240                         /* packed pair-groups: 480 slots >= 465+10 pads */
#define LOG2E 1.4426950408889634f
#define SQRT095 0.97467943448089633f

typedef unsigned long long ull;

__device__ __forceinline__ float ex2f(float x){ float y; asm("ex2.approx.ftz.f32 %0, %1;":"=f"(y):"f"(x)); return y; }
__device__ __forceinline__ float lg2f(float x){ float y; asm("lg2.approx.ftz.f32 %0, %1;":"=f"(y):"f"(x)); return y; }
__device__ __forceinline__ float sqrt_apx(float x){ float y; asm("sqrt.approx.ftz.f32 %0, %1;":"=f"(y):"f"(x)); return y; }
__device__ __forceinline__ float rsqrt_apx(float x){ float y; asm("rsqrt.approx.ftz.f32 %0, %1;":"=f"(y):"f"(x)); return y; }

__device__ __forceinline__ ull pk2(float lo, float hi){ ull r; asm("mov.b64 %0,{%1,%2};":"=l"(r):"f"(lo),"f"(hi)); return r; }
__device__ __forceinline__ void upk2(ull v, float& lo, float& hi){ asm("mov.b64 {%0,%1},%2;":"=f"(lo),"=f"(hi):"l"(v)); }
__device__ __forceinline__ ull fma2(ull a, ull b, ull c){ ull d; asm("fma.rn.f32x2 %0,%1,%2,%3;":"=l"(d):"l"(a),"l"(b),"l"(c)); return d; }
__device__ __forceinline__ ull mul2(ull a, ull b){ ull d; asm("mul.rn.f32x2 %0,%1,%2;":"=l"(d):"l"(a),"l"(b)); return d; }

__global__ __launch_bounds__(AWARPS*32) void aev_kernel(
    const float* __restrict__ coords,
    const float* __restrict__ etaR_p,
    const float* __restrict__ shfR_p,
    const float* __restrict__ etaA_p,
    const float* __restrict__ zeta_p,
    const float* __restrict__ shfA_p,
    const float* __restrict__ shfZ_p,
    const int*   __restrict__ species,
    float* __restrict__ out)
{
    __shared__ float s_cx[NATOMS], s_cy[NATOMS], s_cz[NATOMS];
    __shared__ int   s_sp[NATOMS];
    __shared__ float s_shfR[NSHFR], s_shfA[NSHFA];
    __shared__ float s_cosZ[NSHFZ], s_sinZ[NSHFZ];
    __shared__ __align__(16) float4 s_n4[NATOMS];  // ux,uy,uz (x sqrt095), 0.5*d
    __shared__ float  s_nlg[NATOMS];         // lg2(fcA)
    __shared__ int    s_nsp[NATOMS];
    // pair records: cs = [c0,c1,st0,st1] per group k (2 ulls, v2-loadable)
    //               ex = [e0(2k),e0(2k+1),e1...,e3(2k+1)] per group k (4 ulls)
    __shared__ __align__(16) ull s_cs[2*KMAX];
    __shared__ __align__(16) ull s_ex[4*KMAX];
    __shared__ int    s_pos[NPAIRBIN];
    __shared__ __align__(16) float s_accA[ANG_FEAT];
    __shared__ __align__(16) float s_accR[AWARPS][RAD_FEAT];
    __shared__ float  s_etaR, s_etaA, s_zeta;

    const int tid  = threadIdx.x;
    const int w    = tid >> 5;
    const int lane = tid & 31;
    const int b    = blockIdx.x >> 5;        // 32 blocks per molecule
    const int i    = blockIdx.x & 31;        // this block's atom

    // ---- block-wide loads ----
    if (tid < NATOMS) {
        s_cx[tid] = coords[(b*NATOMS + tid)*3 + 0];
        s_cy[tid] = coords[(b*NATOMS + tid)*3 + 1];
        s_cz[tid] = coords[(b*NATOMS + tid)*3 + 2];
        s_sp[tid] = species[b*NATOMS + tid];
    } else if (tid < 32 + NSHFR) {
        s_shfR[tid-32] = shfR_p[tid-32];
    } else if (tid < 48 + NSHFA) {
        s_shfA[tid-48] = shfA_p[tid-48];
    } else if (tid < 55) {
        if (tid == 52) s_etaR = etaR_p[0];
        if (tid == 53) s_etaA = etaA_p[0];
        if (tid == 54) s_zeta = zeta_p[0];
    } else if (tid >= 56 && tid < 64) {
        float z = shfZ_p[tid-56];
        s_cosZ[tid-56] = __cosf(z);
        s_sinZ[tid-56] = __sinf(z);
    }
    // zero accumulators (FULL coverage: 80 float4 angular + 64 float4 radial)
    if (tid < 80) ((float4*)s_accA)[tid] = make_float4(0.f,0.f,0.f,0.f);
    if (tid < 64) ((float4*)&s_accR[0][0])[tid] = make_float4(0.f,0.f,0.f,0.f);
    __syncthreads();

    const float zeta  = s_zeta;
    const float nEtaR = -s_etaR * LOG2E;
    const float nEtaA = -s_etaA * LOG2E;
    const bool  z32   = (fabsf(zeta - 32.0f) < 1e-4f);
    const float PI_RCR = 3.14159265358979323846f / RCR;
    const float PI_RCA = 3.14159265358979323846f / RCA;

    // ---- candidate neighbor j = lane ----
    const float cix = s_cx[i], ciy = s_cy[i], ciz = s_cz[i];
    const bool  valid_i = (s_sp[i] >= 0);

    float vx = s_cx[lane] - cix;
    float vy = s_cy[lane] - ciy;
    float vz = s_cz[lane] - ciz;
    float d2 = vx*vx + vy*vy + vz*vz;
    float inv = rsqrt_apx(fmaxf(d2, 1e-24f));
    float d   = d2 * inv;
    int   spl = s_sp[lane];
    int   spc = min(max(spl, 0), NSP-1);
    bool  pair_ok = valid_i && (spl >= 0) && (lane != i);

    // ---- radial: 4 shifts per warp, staggered shared atomics ----
    if (pair_ok && d <= RCR) {
        float fcR  = fmaf(0.5f, __cosf(d * PI_RCR), 0.5f);
        float base = 0.25f * fcR;
        float* rad = &s_accR[w][spc * NSHFR];
        int r0 = lane & 15;
        #pragma unroll
        for (int k = w*4; k < w*4 + 4; k++) {
            int r = (r0 + k) & 15;
            float e = d - s_shfR[r];
            atomicAdd(&rad[r], base * ex2f(nEtaR * (e * e)));
        }
    }

    // ---- species-sorted neighbor compaction (warp 0 writes) ----
    bool isnb = pair_ok && (d <= RCA);
    unsigned ms[NSP];
    #pragma unroll
    for (int s = 0; s < NSP; s++)
        ms[s] = __ballot_sync(0xffffffffu, isnb && (spc == s));

    int o1 = __popc(ms[0]);
    int o2 = o1 + __popc(ms[1]);
    int o3 = o2 + __popc(ms[2]);
    int ncA = o3 + __popc(ms[3]);

    if (w == 0 && isnb) {
        unsigned lt = (1u << lane) - 1u;
        int base = (spc == 0) ? 0 : (spc == 1) ? o1 : (spc == 2) ? o2 : o3;
        int pos = base + __popc(ms[spc] & lt);
        float fcA = fmaf(0.5f, __cosf(d * PI_RCA), 0.5f);
        float us  = inv * SQRT095;
        s_n4[pos]  = make_float4(vx*us, vy*us, vz*us, 0.5f*d);
        s_nlg[pos] = lg2f(fcA);
        s_nsp[pos] = spc;
    }

    // ---- closed-form bin counts & even-padded offsets (registers) ----
    const int n0 = o1, n1 = o2-o1, n2 = o3-o2, n3 = ncA-o3;
    int cnt[NPAIRBIN];
    cnt[0] = (n0*(n0-1))>>1; cnt[1] = n0*n1; cnt[2] = n0*n2; cnt[3] = n0*n3;
    cnt[4] = (n1*(n1-1))>>1; cnt[5] = n1*n2; cnt[6] = n1*n3;
    cnt[7] = (n2*(n2-1))>>1; cnt[8] = n2*n3;
    cnt[9] = (n3*(n3-1))>>1;
    int off[NPAIRBIN+1];
    off[0] = 0;
    #pragma unroll
    for (int bb = 0; bb < NPAIRBIN; bb++) off[bb+1] = off[bb] + ((cnt[bb]+1) & ~1);
    const int Ptot = off[NPAIRBIN];

    if (tid < NPAIRBIN) {
        int offv = 0, cv = 0;
        #pragma unroll
        for (int bb = 0; bb < NPAIRBIN; bb++)
            if (tid == bb) { offv = off[bb]; cv = cnt[bb]; }
        s_pos[tid] = offv;
        if (cv & 1) {        // pad record: everything zero -> y32 finite * 0 = 0
            int s = offv + cv, k = s >> 1, h = s & 1;
            float* csf = (float*)s_cs;
            float* exf = (float*)s_ex;
            csf[k*4 + h] = 0.0f; csf[k*4 + 2 + h] = 0.0f;
            #pragma unroll
            for (int p = 0; p < NSHFA; p++) exf[k*8 + p*2 + h] = 0.0f;
        }
    }
    __syncthreads();

    // ---- geometry: one lane per pair; compute 4 exps pair-parallel ----
    const int P = (ncA * (ncA - 1)) >> 1;
    const float zoff = z32 ? -31.0f : 1.0f;  // lg2(2*fa*fb) = 1 + ..., minus 32 if folded
    {
        const float fn1 = (float)(2*ncA - 1);
        float* csf = (float*)s_cs;
        float* exf = (float*)s_ex;
        for (int g = tid; g < P; g += AWARPS*32) {
            float sdisc = sqrtf(fmaf(fn1, fn1, (float)(-8*g)));
            int a = (int)(0.5f * (fn1 - sdisc));
            a = max(a, 0);
            while (a*(ncA-1) - ((a*(a-1))>>1) > g) a--;
            while ((a+1)*(ncA-1) - (((a+1)*a)>>1) <= g) a++;
            int q = g - (a*(ncA-1) - ((a*(a-1))>>1)) + a + 1;

            float4 A4 = s_n4[a];
            float4 B4 = s_n4[q];
            float c  = A4.x*B4.x + A4.y*B4.y + A4.z*B4.z;   // 0.95*cos(theta)
            float st = sqrt_apx(fmaf(-c, c, 1.0f));
            float dm = A4.w + B4.w;
            float lg = s_nlg[a] + s_nlg[q] + zoff;
            int sa = s_nsp[a], sq = s_nsp[q];
            int lo = min(sa, sq), hi = max(sa, sq);
            int pbin = lo*NSP - ((lo*(lo-1))>>1) + (hi - lo);
            int slot = atomicAdd(&s_pos[pbin], 1);
            int k = slot >> 1, h = slot & 1;
            csf[k*4 + h]     = c;
            csf[k*4 + 2 + h] = st;
            #pragma unroll
            for (int p = 0; p < NSHFA; p++) {
                float e = dm - s_shfA[p];
                exf[k*8 + p*2 + h] = ex2f(fmaf(nEtaA * e, e, lg));
            }
        }
    }
    __syncthreads();

    // ---- consume: MUFU-free packed loop; warp w sweeps its quarter ----
    const int p_l = lane >> 3;               // ShfA index owned by lane
    const float cZ = s_cosZ[lane & 7];
    const float sZ = s_sinZ[lane & 7];

    const int g0 = ((Ptot * w) >> 2) & ~1;
    const int g1 = (w == 3) ? Ptot : (((Ptot * (w+1)) >> 2) & ~1);

    if (z32) {
        const ull cZ2 = pk2(cZ, cZ), sZ2 = pk2(sZ, sZ);
        const ull one2 = pk2(1.0f, 1.0f);
        #pragma unroll
        for (int bin = 0; bin < NPAIRBIN; bin++) {
            int lo = max(off[bin], g0), hi = min(off[bin+1], g1);
            if (lo >= hi) continue;
            int k0 = lo >> 1, k1 = hi >> 1;
            ull r2 = 0;
            #pragma unroll 2
            for (int k = k0; k < k1; k++) {
                ulonglong2 cs = *((const ulonglong2*)s_cs + k);  // LDS.128 (c2, s2)
                ull e2 = s_ex[k*4 + p_l];                        // LDS.64, 4 addrs/warp
                ull t2 = fma2(cs.y, sZ2, one2);
                ull y  = fma2(cs.x, cZ2, t2);       // 1 + cos(theta - ShfZ)
                ull yy2 = mul2(y, y);
                ull y4 = mul2(yy2, yy2);
                ull y8 = mul2(y4, y4);
                ull y16 = mul2(y8, y8);
                ull y32 = mul2(y16, y16);
                r2 = fma2(y32, e2, r2);
            }
            float rlo, rhi; upk2(r2, rlo, rhi);
            atomicAdd(&s_accA[bin*32 + lane], rlo + rhi);
        }
    } else {
        const float* csf = (const float*)s_cs;
        const float* exf = (const float*)s_ex;
        #pragma unroll
        for (int bin = 0; bin < NPAIRBIN; bin++) {
            int lo = max(off[bin], g0), hi = min(off[bin+1], g1);
            if (lo >= hi) continue;
            float r = 0.0f;
            for (int g = lo; g < hi; g++) {
                int k = g >> 1, h = g & 1;
                float c  = csf[k*4 + h];
                float st = csf[k*4 + 2 + h];
                float e  = exf[k*8 + p_l*2 + h];
                float t = fmaf(st, sZ, 1.0f);
                float y = fmaf(c, cZ, t);
                float f1 = __powf(0.5f * y, zeta);
                r = fmaf(f1, e, r);
            }
            atomicAdd(&s_accA[bin*32 + lane], r);
        }
    }
    __syncthreads();

    // ---- write 384 features (radial: sum 4 banks; angular: direct) ----
    float* op = out + (size_t)(b*NATOMS + i) * OUT_FEAT;
    #pragma unroll
    for (int f = w*96 + lane; f < w*96 + 96; f += 32) {
        float v;
        if (f < RAD_FEAT)
            v = (s_accR[0][f] + s_accR[1][f]) + (s_accR[2][f] + s_accR[3][f]);
        else
            v = s_accA[f - RAD_FEAT];
        op[f] = v;
    }
}

extern "C" void kernel_launch(void* const* d_in, const int* in_sizes, int n_in,
                              void* d_out, int out_size)
{
    const float* coords = (const float*)d_in[0];
    const float* etaR   = (const float*)d_in[1];
    const float* shfR   = (const float*)d_in[2];
    const float* etaA   = (const float*)d_in[3];
    const float* zeta   = (const float*)d_in[4];
    const float* shfA   = (const float*)d_in[5];
    const float* shfZ   = (const float*)d_in[6];
    const int*   spec   = (const int*)d_in[7];
    float* out = (float*)d_out;

    int B = in_sizes[0] / (NATOMS*3);
    dim3 grid(B * NATOMS);   // 1 atom per block, 4 warps
    aev_kernel<<<grid, AWARPS*32>>>(coords, etaR, shfR, etaA, zeta, shfA, shfZ, spec, out);
}